// round 14
// baseline (speedup 1.0000x reference)
#include <cuda_runtime.h>
#include <cuda_fp16.h>
#include <cstdint>

#define NN 50000
#define EE 400000
#define RR 3
#define DD 128
#define HH 8
#define RN (RR*NN)
#define RE (RR*EE)
#define NEG_SLOPE 0.2f
#define LN_EPS 1e-5f

// ---------------- scratch (device globals; no allocs allowed) ----------------
__device__ __align__(128) __half g_hp[(size_t)RR*NN*DD];
__device__ __align__(128) float g_el[(size_t)RN*HH];
__device__ __align__(128) float g_er[(size_t)RN*HH];
__device__ __align__(128) float g_h1[(size_t)NN*DD];
__device__ __align__(128) __half g_xh[(size_t)NN*DD];   // fp16 GEMM input
__device__ __align__(128) int   g_off[RN];
__device__ __align__(128) int   g_deg[RN];
__device__ __align__(128) int   g_cnt[RN];
__device__ __align__(128) int   g_csr[RE];      // src node ids
__device__ int g_gcur;
// pre-built B mma fragments (fp16): [slot(7)][ks(8)][n16(8)][lane(32)][reg(4)]
__device__ __align__(128) uint32_t g_wf[7*8*8*32*4];

__device__ __forceinline__ uint32_t smem_u32(const void* p) {
    uint32_t a;
    asm("{ .reg .u64 t; cvta.to.shared.u64 t, %1; cvt.u32.u64 %0, t; }" : "=r"(a) : "l"(p));
    return a;
}

#define LDSM4(R, A) \
    asm volatile("ldmatrix.sync.aligned.m8n8.x4.shared.b16 {%0,%1,%2,%3}, [%4];" \
        : "=r"((R)[0]), "=r"((R)[1]), "=r"((R)[2]), "=r"((R)[3]) : "r"(A))

#define MMA(C, A, B0, B1) \
    asm volatile("mma.sync.aligned.m16n8k16.row.col.f32.f16.f16.f32 " \
        "{%0,%1,%2,%3}, {%4,%5,%6,%7}, {%8,%9}, {%0,%1,%2,%3};" \
        : "+f"((C)[0]), "+f"((C)[1]), "+f"((C)[2]), "+f"((C)[3]) \
        : "r"((A)[0]), "r"((A)[1]), "r"((A)[2]), "r"((A)[3]), "r"(B0), "r"(B1))

#define MMA_BLOCK_P(acc, ah, b, p) do {             \
    MMA(acc[0][2*(p)],   ah[0], b[0], b[1]);        \
    MMA(acc[0][2*(p)+1], ah[0], b[2], b[3]);        \
    MMA(acc[1][2*(p)],   ah[1], b[0], b[1]);        \
    MMA(acc[1][2*(p)+1], ah[1], b[2], b[3]);        \
} while (0)

__device__ __forceinline__ uint32_t pack_h2(__half a, __half b) {
    uint16_t lo = *(uint16_t*)&a, hi = *(uint16_t*)&b;
    return (uint32_t)lo | ((uint32_t)hi << 16);
}

// ---------------- setup: zero cnt/cursor + weight fragments + feat convert ---
__global__ void k_setup(const float* __restrict__ W1, const float* __restrict__ W2,
                        const float* __restrict__ Wc1, const float* __restrict__ X)
{
    int i = blockIdx.x*blockDim.x + threadIdx.x;
    if (i == 0) g_gcur = 0;
    if (i < RN) g_cnt[i] = 0;

    if (i < 7*8*8*32) {
        int lane = i & 31;
        int rem  = i >> 5;
        int p16  = rem & 7;  rem >>= 3;
        int ks   = rem & 7;  rem >>= 3;
        int slot = rem;
        const float* Wsrc = (slot < 3) ? W1 + (size_t)slot*16384
                          : (slot < 6) ? W2 + (size_t)(slot-3)*16384
                          : Wc1;
        uint32_t fh[4];
        #pragma unroll
        for (int j = 0; j < 4; j++) {
            int n = p16*16 + (j>>1)*8 + (lane>>2);
            int k = ks*16  + (j&1)*8  + (lane&3)*2;
            float w0 = Wsrc[(size_t)k*128 + n];
            float w1 = Wsrc[(size_t)(k+1)*128 + n];
            fh[j] = pack_h2(__float2half_rn(w0), __float2half_rn(w1));
        }
        size_t base = (((size_t)slot*8 + ks)*8 + p16)*128 + (size_t)lane*4;
        *(uint4*)&g_wf[base] = make_uint4(fh[0], fh[1], fh[2], fh[3]);
    }

    if (i < NN*16) {
        const float* xp = X + (size_t)i*8;
        float4 a = *(const float4*)xp, b = *(const float4*)(xp+4);
        float v[8] = {a.x,a.y,a.z,a.w,b.x,b.y,b.z,b.w};
        __half hh[8];
        #pragma unroll
        for (int t = 0; t < 8; t++) hh[t] = __float2half_rn(v[t]);
        *(uint4*)&g_xh[(size_t)i*8] = *(const uint4*)hh;
    }
}

// ---------------- CSR build (count -> assign -> fill) ----------------
__global__ void k_count(const int* __restrict__ edst) {
    int i = blockIdx.x*blockDim.x + threadIdx.x;
    if (i < RE) atomicAdd(&g_cnt[(i/EE)*NN + edst[i]], 1);
}
__device__ __forceinline__ int warp_incl_scan(int v) {
    int lane = threadIdx.x & 31;
    #pragma unroll
    for (int o = 1; o < 32; o <<= 1) {
        int t = __shfl_up_sync(0xffffffffu, v, o);
        if (lane >= o) v += t;
    }
    return v;
}
// unordered-but-contiguous segment reservation: one cursor atomic per warp
__global__ void k_assign() {
    int i = blockIdx.x*blockDim.x + threadIdx.x;
    int lane = threadIdx.x & 31;
    int v = (i < RN) ? g_cnt[i] : 0;
    int incl = warp_incl_scan(v);
    int total = __shfl_sync(0xffffffffu, incl, 31);
    int base = 0;
    if (lane == 31) base = atomicAdd(&g_gcur, total);
    base = __shfl_sync(0xffffffffu, base, 31);
    int off = base + incl - v;
    if (i < RN) {
        g_off[i] = off;
        g_deg[i] = v;
        g_cnt[i] = off;    // fill cursor
    }
}
__global__ void k_fill(const int* __restrict__ esrc, const int* __restrict__ edst) {
    int i = blockIdx.x*blockDim.x + threadIdx.x;
    if (i < RE) {
        int idx = (i/EE)*NN + edst[i];
        int p = atomicAdd(&g_cnt[idx], 1);
        g_csr[p] = esrc[i];
    }
}

// ---------------- projection GEMM: fp16 single-term, coalesced epilogue ------
#define ASTRA 136
#define SM_PROJ (128*ASTRA*2 + 16*1024 + 1024)
#define SM_CLS  (128*ASTRA*2 + 2048)

__global__ void __launch_bounds__(256, 2)
k_proj(int slot0, const float* __restrict__ al, const float* __restrict__ ar)
{
    extern __shared__ char smem[];
    __half* Ah = (__half*)smem;                 // [128][136]
    float* Ps = (float*)(smem + 128*ASTRA*2 + 16*1024);

    const int tid  = threadIdx.x;
    const int lane = tid & 31;
    const int w    = tid >> 5;
    const int wm   = w & 3;
    const int wn   = w >> 2;
    const int r    = blockIdx.y;
    const int slot = slot0 + r;
    const int n0   = blockIdx.x * 128;

    Ps[tid] = (tid < 128) ? al[r*128 + tid] : ar[r*128 + tid - 128];

    #pragma unroll
    for (int i = 0; i < 4; i++) {
        int idx = tid + i*256;
        int m = idx >> 3, k = (idx & 7) << 4;
        int gm = n0 + m;
        uint4 z0 = make_uint4(0,0,0,0), z1 = z0;
        if (gm < NN) {
            z0 = *(const uint4*)&g_xh[(size_t)gm*128 + k];
            z1 = *(const uint4*)&g_xh[(size_t)gm*128 + k + 8];
        }
        *(uint4*)&Ah[m*ASTRA + k]     = z0;
        *(uint4*)&Ah[m*ASTRA + k + 8] = z1;
    }
    __syncthreads();

    const uint32_t sAh = smem_u32(Ah);
    const uint32_t aOff = ((wm*32 + (lane & 15))*ASTRA + (lane >> 4)*8) * 2;
    const uint32_t* wf = g_wf + (size_t)slot*8*8*128;

    float acc[2][8][4];
    #pragma unroll
    for (int mt = 0; mt < 2; mt++)
        #pragma unroll
        for (int nt = 0; nt < 8; nt++)
            #pragma unroll
            for (int q = 0; q < 4; q++) acc[mt][nt][q] = 0.f;

    #pragma unroll 2
    for (int ks = 0; ks < 8; ks++) {
        uint32_t ah[2][4];
        uint4 b4[4];
        #pragma unroll
        for (int p = 0; p < 4; p++)
            b4[p] = __ldg((const uint4*)(wf + (ks*8 + wn*4 + p)*128) + lane);
        #pragma unroll
        for (int mt = 0; mt < 2; mt++)
            LDSM4(ah[mt], sAh + aOff + mt*(16*ASTRA*2) + ks*32);
        #pragma unroll
        for (int p = 0; p < 4; p++) {
            uint32_t b[4] = {b4[p].x, b4[p].y, b4[p].z, b4[p].w};
            MMA_BLOCK_P(acc, ah, b, p);
        }
    }

    // ---- epilogue: stage tile + el/er in smem, copy coalesced ----
    __syncthreads();
    __half* Ts  = (__half*)smem;                        // [128][136]
    float*  Els = (float*)(smem + 128*ASTRA*2);         // 128x8
    float*  Ers = Els + 128*8;                          // 128x8

    const int g  = lane >> 2;
    const int c2 = (lane & 3) * 2;
    #pragma unroll
    for (int mt = 0; mt < 2; mt++) {
        #pragma unroll
        for (int rh = 0; rh < 2; rh++) {
            int row = wm*32 + mt*16 + rh*8 + g;
            #pragma unroll
            for (int nt = 0; nt < 8; nt++) {
                int n = wn*64 + nt*8 + c2;
                *(__half2*)&Ts[row*ASTRA + n] =
                    __floats2half2_rn(acc[mt][nt][rh*2], acc[mt][nt][rh*2+1]);
            }
            #pragma unroll
            for (int j = 0; j < 4; j++) {
                float el = 0.f, er = 0.f;
                #pragma unroll
                for (int t = 0; t < 2; t++) {
                    int nt = 2*j + t;
                    int n = wn*64 + nt*8 + c2;
                    float v0 = acc[mt][nt][rh*2], v1 = acc[mt][nt][rh*2+1];
                    el += v0*Ps[n] + v1*Ps[n+1];
                    er += v0*Ps[128+n] + v1*Ps[128+n+1];
                }
                el += __shfl_xor_sync(0xffffffffu, el, 1);
                er += __shfl_xor_sync(0xffffffffu, er, 1);
                el += __shfl_xor_sync(0xffffffffu, el, 2);
                er += __shfl_xor_sync(0xffffffffu, er, 2);
                if ((lane & 3) == 0) {
                    Els[row*8 + wn*4 + j] = el;
                    Ers[row*8 + wn*4 + j] = er;
                }
            }
        }
    }
    __syncthreads();

    #pragma unroll
    for (int i = 0; i < 8; i++) {
        int idx = tid + i*256;
        int row = idx >> 4, cc = idx & 15;
        int gm = n0 + row;
        if (gm < NN)
            *(uint4*)&g_hp[((size_t)r*NN + gm)*128 + cc*8] = *(const uint4*)&Ts[row*ASTRA + cc*8];
    }
    #pragma unroll
    for (int i = 0; i < 4; i++) {
        int idx = tid + i*256;
        int row = idx >> 3;
        if (n0 + row < NN) {
            g_el[((size_t)r*NN + n0)*8 + idx] = Els[idx];
            g_er[((size_t)r*NN + n0)*8 + idx] = Ers[idx];
        }
    }
}

// ---------------- classifier GEMM ----------------
__global__ void __launch_bounds__(256, 2)
k_cls(const float* __restrict__ bc1, const float* __restrict__ wc2,
      const float* __restrict__ bc2, float* __restrict__ out1)
{
    extern __shared__ char smem[];
    __half* Ah = (__half*)smem;
    float* Ps = (float*)(smem + 128*ASTRA*2);
    float* Pt = Ps + 256;

    const int tid  = threadIdx.x;
    const int lane = tid & 31;
    const int w    = tid >> 5;
    const int wm   = w & 3;
    const int wn   = w >> 2;
    const int n0   = blockIdx.x * 128;

    Ps[tid] = (tid < 128) ? bc1[tid] : wc2[tid - 128];

    #pragma unroll
    for (int i = 0; i < 4; i++) {
        int idx = tid + i*256;
        int m = idx >> 3, k = (idx & 7) << 4;
        int gm = n0 + m;
        uint4 z0 = make_uint4(0,0,0,0), z1 = z0;
        if (gm < NN) {
            z0 = *(const uint4*)&g_xh[(size_t)gm*128 + k];
            z1 = *(const uint4*)&g_xh[(size_t)gm*128 + k + 8];
        }
        *(uint4*)&Ah[m*ASTRA + k]     = z0;
        *(uint4*)&Ah[m*ASTRA + k + 8] = z1;
    }
    __syncthreads();

    const uint32_t sAh = smem_u32(Ah);
    const uint32_t aOff = ((wm*32 + (lane & 15))*ASTRA + (lane >> 4)*8) * 2;
    const uint32_t* wf = g_wf + (size_t)6*8*8*128;

    float acc[2][8][4];
    #pragma unroll
    for (int mt = 0; mt < 2; mt++)
        #pragma unroll
        for (int nt = 0; nt < 8; nt++)
            #pragma unroll
            for (int q = 0; q < 4; q++) acc[mt][nt][q] = 0.f;

    #pragma unroll 2
    for (int ks = 0; ks < 8; ks++) {
        uint32_t ah[2][4];
        uint4 b4[4];
        #pragma unroll
        for (int p = 0; p < 4; p++)
            b4[p] = __ldg((const uint4*)(wf + (ks*8 + wn*4 + p)*128) + lane);
        #pragma unroll
        for (int mt = 0; mt < 2; mt++)
            LDSM4(ah[mt], sAh + aOff + mt*(16*ASTRA*2) + ks*32);
        #pragma unroll
        for (int p = 0; p < 4; p++) {
            uint32_t b[4] = {b4[p].x, b4[p].y, b4[p].z, b4[p].w};
            MMA_BLOCK_P(acc, ah, b, p);
        }
    }

    const int g  = lane >> 2;
    const int c2 = (lane & 3) * 2;
    #pragma unroll
    for (int mt = 0; mt < 2; mt++) {
        #pragma unroll
        for (int rh = 0; rh < 2; rh++) {
            float s = 0.f;
            #pragma unroll
            for (int nt = 0; nt < 8; nt++) {
                int n = wn*64 + nt*8 + c2;
                s += fmaxf(acc[mt][nt][rh*2]   + Ps[n],   0.f) * Ps[128+n];
                s += fmaxf(acc[mt][nt][rh*2+1] + Ps[n+1], 0.f) * Ps[128+n+1];
            }
            s += __shfl_xor_sync(0xffffffffu, s, 1);
            s += __shfl_xor_sync(0xffffffffu, s, 2);
            if ((lane & 3) == 0)
                Pt[(wm*32 + mt*16 + rh*8 + g)*2 + wn] = s;
        }
    }
    __syncthreads();
    if (tid < 128) {
        int gm = n0 + tid;
        if (gm < NN) out1[gm] = Pt[tid*2] + Pt[tid*2+1] + bc2[0];
    }
}

// ---------------- warp-per-node aggregate: 16 lanes per edge (2 edges/warp) --
__global__ void k_agg(const float* __restrict__ bias,
                      const float* __restrict__ lng, const float* __restrict__ lnb,
                      int mode)
{
    int warp = (blockIdx.x*blockDim.x + threadIdx.x) >> 5;
    if (warp >= NN) return;
    int v = warp;
    int lane = threadIdx.x & 31;
    int half = lane >> 4;       // which edge of the pair
    int sub  = lane & 15;       // position in row
    int h    = sub >> 1;        // head
    int cb   = sub * 8;         // col base (halves)

    float ax[8];
    #pragma unroll
    for (int j = 0; j < 8; j++) ax[j] = 0.f;

    #pragma unroll
    for (int r = 0; r < RR; r++) {
        int base = r*NN + v;
        int st = g_off[base], d = g_deg[base];
        if (d == 0) continue;
        float erv = __ldg(&g_er[(size_t)base*HH + h]);
        const __half* hpr = g_hp + (size_t)r*NN*DD;
        const float*  elr = g_el + (size_t)r*NN*HH;

        float nx[8];
        #pragma unroll
        for (int j = 0; j < 8; j++) nx[j] = 0.f;
        float den = 0.f;

        int i = 0;
        for (; i + 4 <= d; i += 4) {
            int sa = __ldg(&g_csr[st + i + half]);
            int sb = __ldg(&g_csr[st + i + 2 + half]);
            float xa = __ldg(&elr[(size_t)sa*HH + h]) + erv;
            float xb = __ldg(&elr[(size_t)sb*HH + h]) + erv;
            uint4 ua = *(const uint4*)&hpr[(size_t)sa*DD + cb];
            uint4 ub = *(const uint4*)&hpr[(size_t)sb*DD + cb];
            xa = xa > 0.f ? xa : NEG_SLOPE*xa;
            xb = xb > 0.f ? xb : NEG_SLOPE*xb;
            float qa = __expf(xa), qb = __expf(xb);
            den += qa + qb;
            const __half2* ha = (const __half2*)&ua;
            const __half2* hb = (const __half2*)&ub;
            #pragma unroll
            for (int j = 0; j < 4; j++) {
                float2 fa = __half22float2(ha[j]);
                float2 fb = __half22float2(hb[j]);
                nx[2*j]   += qa*fa.x + qb*fb.x;
                nx[2*j+1] += qa*fa.y + qb*fb.y;
            }
        }
        for (; i < d; i += 2) {
            int idx = i + half;
            bool ok = idx < d;
            int s = ok ? __ldg(&g_csr[st + idx]) : 0;
            float x = __ldg(&elr[(size_t)s*HH + h]) + erv;
            x = x > 0.f ? x : NEG_SLOPE*x;
            float q = ok ? __expf(x) : 0.f;
            den += q;
            uint4 u = *(const uint4*)&hpr[(size_t)s*DD + cb];
            const __half2* hu = (const __half2*)&u;
            #pragma unroll
            for (int j = 0; j < 4; j++) {
                float2 f = __half22float2(hu[j]);
                nx[2*j]   += q*f.x;
                nx[2*j+1] += q*f.y;
            }
        }
        den += __shfl_xor_sync(0xffffffffu, den, 16);
        #pragma unroll
        for (int j = 0; j < 8; j++) nx[j] += __shfl_xor_sync(0xffffffffu, nx[j], 16);
        float rd = 1.0f / den;
        #pragma unroll
        for (int j = 0; j < 8; j++) ax[j] += nx[j]*rd;
    }

    #pragma unroll
    for (int j = 0; j < 8; j++) {
        int c = cb + j;
        ax[j] += bias[c] + bias[128+c] + bias[256+c];
    }

    float o[8];
    if (mode == 0) {
        #pragma unroll
        for (int j = 0; j < 8; j++) o[j] = fmaxf(ax[j], 0.f);
        if (half == 0) {
            *(float4*)&g_h1[(size_t)v*DD + cb]     = make_float4(o[0],o[1],o[2],o[3]);
            *(float4*)&g_h1[(size_t)v*DD + cb + 4] = make_float4(o[4],o[5],o[6],o[7]);
        }
    } else {
        const float* h1p = &g_h1[(size_t)v*DD + cb];
        float4 r0 = *(const float4*)h1p;
        float4 r1 = *(const float4*)(h1p + 4);
        ax[0]+=r0.x; ax[1]+=r0.y; ax[2]+=r0.z; ax[3]+=r0.w;
        ax[4]+=r1.x; ax[5]+=r1.y; ax[6]+=r1.z; ax[7]+=r1.w;
        float s = 0.f, ss = 0.f;
        #pragma unroll
        for (int j = 0; j < 8; j++) { s += ax[j]; ss += ax[j]*ax[j]; }
        #pragma unroll
        for (int o2 = 8; o2; o2 >>= 1) {
            s  += __shfl_xor_sync(0xffffffffu, s,  o2);
            ss += __shfl_xor_sync(0xffffffffu, ss, o2);
        }
        float mu  = s * (1.0f/128.0f);
        float var = ss * (1.0f/128.0f) - mu*mu;
        float inv = rsqrtf(var + LN_EPS);
        #pragma unroll
        for (int j = 0; j < 8; j++)
            o[j] = (ax[j] - mu)*inv*lng[cb+j] + lnb[cb+j];
    }
    if (half == 0) {
        __half hh[8];
        #pragma unroll
        for (int j = 0; j < 8; j++) hh[j] = __float2half_rn(o[j]);
        *(uint4*)&g_xh[(size_t)v*DD + cb] = *(const uint4*)hh;
    }
}

// ---------------- launch ----------------
extern "C" void kernel_launch(void* const* d_in, const int* in_sizes, int n_in,
                              void* d_out, int out_size)
{
    const float* feat = (const float*)d_in[0];
    const int*   esrc = (const int*)d_in[1];
    const int*   edst = (const int*)d_in[2];
    const float* W1   = (const float*)d_in[3];
    const float* al1  = (const float*)d_in[4];
    const float* ar1  = (const float*)d_in[5];
    const float* b1   = (const float*)d_in[6];
    const float* W2   = (const float*)d_in[7];
    const float* al2  = (const float*)d_in[8];
    const float* ar2  = (const float*)d_in[9];
    const float* b2   = (const float*)d_in[10];
    const float* lng  = (const float*)d_in[11];
    const float* lnb  = (const float*)d_in[12];
    const float* Wc1  = (const float*)d_in[13];
    const float* bc1  = (const float*)d_in[14];
    const float* Wc2  = (const float*)d_in[15];
    const float* bc2  = (const float*)d_in[16];
    float* out = (float*)d_out;

    cudaFuncSetAttribute(k_proj, cudaFuncAttributeMaxDynamicSharedMemorySize, SM_PROJ);
    cudaFuncSetAttribute(k_cls,  cudaFuncAttributeMaxDynamicSharedMemorySize, SM_CLS);

    int gx = (NN + 127)/128;
    dim3 gp(gx, RR);
    int aggBlocks = (NN*32 + 255)/256;

    k_setup<<<(NN*16 + 255)/256, 256>>>(W1, W2, Wc1, feat);                // 1
    k_count<<<(RE+255)/256, 256>>>(edst);                                  // 2
    k_assign<<<(RN+255)/256, 256>>>();                                     // 3
    k_fill<<<(RE+255)/256, 256>>>(esrc, edst);                             // 4  <-- profiled
    k_proj<<<gp, 256, SM_PROJ>>>(0, al1, ar1);                             // 5
    k_agg<<<aggBlocks, 256>>>(b1, nullptr, nullptr, 0);                    // 6
    k_proj<<<gp, 256, SM_PROJ>>>(3, al2, ar2);                             // 7
    k_agg<<<aggBlocks, 256>>>(b2, lng, lnb, 1);                            // 8
    k_cls<<<gx, 256, SM_CLS>>>(bc1, Wc2, bc2, out);                        // 9
}

// round 15
// speedup vs baseline: 1.0019x; 1.0019x over previous
#include <cuda_runtime.h>
#include <cuda_fp16.h>
#include <cstdint>

#define NN 50000
#define EE 400000
#define RR 3
#define DD 128
#define HH 8
#define RN (RR*NN)
#define RE (RR*EE)
#define NEG_SLOPE 0.2f
#define LN_EPS 1e-5f

// ---------------- scratch (device globals; no allocs allowed) ----------------
__device__ __align__(128) __half g_hp[(size_t)RR*NN*DD];
__device__ __align__(128) float g_el[(size_t)RN*HH];
__device__ __align__(128) float g_er[(size_t)RN*HH];
__device__ __align__(128) float g_h1[(size_t)NN*DD];
__device__ __align__(128) __half g_xh[(size_t)NN*DD];   // fp16 GEMM input
__device__ __align__(128) int   g_off[RN];
__device__ __align__(128) int   g_deg[RN];
__device__ __align__(128) int   g_cnt[RN];
__device__ __align__(128) int   g_csr[RE];      // src node ids
__device__ int g_gcur;
// pre-built B mma fragments (fp16): [slot(7)][ks(8)][n16(8)][lane(32)][reg(4)]
__device__ __align__(128) uint32_t g_wf[7*8*8*32*4];

__device__ __forceinline__ uint32_t smem_u32(const void* p) {
    uint32_t a;
    asm("{ .reg .u64 t; cvta.to.shared.u64 t, %1; cvt.u32.u64 %0, t; }" : "=r"(a) : "l"(p));
    return a;
}

#define LDSM4(R, A) \
    asm volatile("ldmatrix.sync.aligned.m8n8.x4.shared.b16 {%0,%1,%2,%3}, [%4];" \
        : "=r"((R)[0]), "=r"((R)[1]), "=r"((R)[2]), "=r"((R)[3]) : "r"(A))

#define MMA(C, A, B0, B1) \
    asm volatile("mma.sync.aligned.m16n8k16.row.col.f32.f16.f16.f32 " \
        "{%0,%1,%2,%3}, {%4,%5,%6,%7}, {%8,%9}, {%0,%1,%2,%3};" \
        : "+f"((C)[0]), "+f"((C)[1]), "+f"((C)[2]), "+f"((C)[3]) \
        : "r"((A)[0]), "r"((A)[1]), "r"((A)[2]), "r"((A)[3]), "r"(B0), "r"(B1))

#define MMA_BLOCK_P(acc, ah, b, p) do {             \
    MMA(acc[0][2*(p)],   ah[0], b[0], b[1]);        \
    MMA(acc[0][2*(p)+1], ah[0], b[2], b[3]);        \
    MMA(acc[1][2*(p)],   ah[1], b[0], b[1]);        \
    MMA(acc[1][2*(p)+1], ah[1], b[2], b[3]);        \
} while (0)

__device__ __forceinline__ uint32_t pack_h2(__half a, __half b) {
    uint16_t lo = *(uint16_t*)&a, hi = *(uint16_t*)&b;
    return (uint32_t)lo | ((uint32_t)hi << 16);
}

// ---------------- setup: zero cnt/cursor + weight fragments + feat convert ---
__global__ void k_setup(const float* __restrict__ W1, const float* __restrict__ W2,
                        const float* __restrict__ Wc1, const float* __restrict__ X)
{
    int i = blockIdx.x*blockDim.x + threadIdx.x;
    if (i == 0) g_gcur = 0;
    if (i < RN) g_cnt[i] = 0;

    if (i < 7*8*8*32) {
        int lane = i & 31;
        int rem  = i >> 5;
        int p16  = rem & 7;  rem >>= 3;
        int ks   = rem & 7;  rem >>= 3;
        int slot = rem;
        const float* Wsrc = (slot < 3) ? W1 + (size_t)slot*16384
                          : (slot < 6) ? W2 + (size_t)(slot-3)*16384
                          : Wc1;
        uint32_t fh[4];
        #pragma unroll
        for (int j = 0; j < 4; j++) {
            int n = p16*16 + (j>>1)*8 + (lane>>2);
            int k = ks*16  + (j&1)*8  + (lane&3)*2;
            float w0 = Wsrc[(size_t)k*128 + n];
            float w1 = Wsrc[(size_t)(k+1)*128 + n];
            fh[j] = pack_h2(__float2half_rn(w0), __float2half_rn(w1));
        }
        size_t base = (((size_t)slot*8 + ks)*8 + p16)*128 + (size_t)lane*4;
        *(uint4*)&g_wf[base] = make_uint4(fh[0], fh[1], fh[2], fh[3]);
    }

    if (i < NN*16) {
        const float* xp = X + (size_t)i*8;
        float4 a = *(const float4*)xp, b = *(const float4*)(xp+4);
        float v[8] = {a.x,a.y,a.z,a.w,b.x,b.y,b.z,b.w};
        __half hh[8];
        #pragma unroll
        for (int t = 0; t < 8; t++) hh[t] = __float2half_rn(v[t]);
        *(uint4*)&g_xh[(size_t)i*8] = *(const uint4*)hh;
    }
}

// ---------------- CSR build (count -> assign -> fill) ----------------
__global__ void k_count(const int* __restrict__ edst) {
    int i = blockIdx.x*blockDim.x + threadIdx.x;
    if (i < RE) atomicAdd(&g_cnt[(i/EE)*NN + edst[i]], 1);
}
__device__ __forceinline__ int warp_incl_scan(int v) {
    int lane = threadIdx.x & 31;
    #pragma unroll
    for (int o = 1; o < 32; o <<= 1) {
        int t = __shfl_up_sync(0xffffffffu, v, o);
        if (lane >= o) v += t;
    }
    return v;
}
// unordered-but-contiguous segment reservation: one cursor atomic per warp
__global__ void k_assign() {
    int i = blockIdx.x*blockDim.x + threadIdx.x;
    int lane = threadIdx.x & 31;
    int v = (i < RN) ? g_cnt[i] : 0;
    int incl = warp_incl_scan(v);
    int total = __shfl_sync(0xffffffffu, incl, 31);
    int base = 0;
    if (lane == 31) base = atomicAdd(&g_gcur, total);
    base = __shfl_sync(0xffffffffu, base, 31);
    int off = base + incl - v;
    if (i < RN) {
        g_off[i] = off;
        g_deg[i] = v;
        g_cnt[i] = off;    // fill cursor
    }
}
__global__ void k_fill(const int* __restrict__ esrc, const int* __restrict__ edst) {
    int i = blockIdx.x*blockDim.x + threadIdx.x;
    if (i < RE) {
        int idx = (i/EE)*NN + edst[i];
        int p = atomicAdd(&g_cnt[idx], 1);
        g_csr[p] = esrc[i];
    }
}

// ---------------- projection GEMM: fp16 single-term, coalesced epilogue ------
#define ASTRA 136
#define SM_PROJ (128*ASTRA*2 + 16*1024 + 1024)
#define SM_CLS  (128*ASTRA*2 + 2048)

__global__ void __launch_bounds__(256, 2)
k_proj(int slot0, const float* __restrict__ al, const float* __restrict__ ar)
{
    extern __shared__ char smem[];
    __half* Ah = (__half*)smem;                 // [128][136]
    float* Ps = (float*)(smem + 128*ASTRA*2 + 16*1024);

    const int tid  = threadIdx.x;
    const int lane = tid & 31;
    const int w    = tid >> 5;
    const int wm   = w & 3;
    const int wn   = w >> 2;
    const int r    = blockIdx.y;
    const int slot = slot0 + r;
    const int n0   = blockIdx.x * 128;

    Ps[tid] = (tid < 128) ? al[r*128 + tid] : ar[r*128 + tid - 128];

    #pragma unroll
    for (int i = 0; i < 4; i++) {
        int idx = tid + i*256;
        int m = idx >> 3, k = (idx & 7) << 4;
        int gm = n0 + m;
        uint4 z0 = make_uint4(0,0,0,0), z1 = z0;
        if (gm < NN) {
            z0 = *(const uint4*)&g_xh[(size_t)gm*128 + k];
            z1 = *(const uint4*)&g_xh[(size_t)gm*128 + k + 8];
        }
        *(uint4*)&Ah[m*ASTRA + k]     = z0;
        *(uint4*)&Ah[m*ASTRA + k + 8] = z1;
    }
    __syncthreads();

    const uint32_t sAh = smem_u32(Ah);
    const uint32_t aOff = ((wm*32 + (lane & 15))*ASTRA + (lane >> 4)*8) * 2;
    const uint32_t* wf = g_wf + (size_t)slot*8*8*128;

    float acc[2][8][4];
    #pragma unroll
    for (int mt = 0; mt < 2; mt++)
        #pragma unroll
        for (int nt = 0; nt < 8; nt++)
            #pragma unroll
            for (int q = 0; q < 4; q++) acc[mt][nt][q] = 0.f;

    #pragma unroll 2
    for (int ks = 0; ks < 8; ks++) {
        uint32_t ah[2][4];
        uint4 b4[4];
        #pragma unroll
        for (int p = 0; p < 4; p++)
            b4[p] = __ldg((const uint4*)(wf + (ks*8 + wn*4 + p)*128) + lane);
        #pragma unroll
        for (int mt = 0; mt < 2; mt++)
            LDSM4(ah[mt], sAh + aOff + mt*(16*ASTRA*2) + ks*32);
        #pragma unroll
        for (int p = 0; p < 4; p++) {
            uint32_t b[4] = {b4[p].x, b4[p].y, b4[p].z, b4[p].w};
            MMA_BLOCK_P(acc, ah, b, p);
        }
    }

    // ---- epilogue: stage tile + el/er in smem, copy coalesced ----
    __syncthreads();
    __half* Ts  = (__half*)smem;                        // [128][136]
    float*  Els = (float*)(smem + 128*ASTRA*2);         // 128x8
    float*  Ers = Els + 128*8;                          // 128x8

    const int g  = lane >> 2;
    const int c2 = (lane & 3) * 2;
    #pragma unroll
    for (int mt = 0; mt < 2; mt++) {
        #pragma unroll
        for (int rh = 0; rh < 2; rh++) {
            int row = wm*32 + mt*16 + rh*8 + g;
            #pragma unroll
            for (int nt = 0; nt < 8; nt++) {
                int n = wn*64 + nt*8 + c2;
                *(__half2*)&Ts[row*ASTRA + n] =
                    __floats2half2_rn(acc[mt][nt][rh*2], acc[mt][nt][rh*2+1]);
            }
            #pragma unroll
            for (int j = 0; j < 4; j++) {
                float el = 0.f, er = 0.f;
                #pragma unroll
                for (int t = 0; t < 2; t++) {
                    int nt = 2*j + t;
                    int n = wn*64 + nt*8 + c2;
                    float v0 = acc[mt][nt][rh*2], v1 = acc[mt][nt][rh*2+1];
                    el += v0*Ps[n] + v1*Ps[n+1];
                    er += v0*Ps[128+n] + v1*Ps[128+n+1];
                }
                el += __shfl_xor_sync(0xffffffffu, el, 1);
                er += __shfl_xor_sync(0xffffffffu, er, 1);
                el += __shfl_xor_sync(0xffffffffu, el, 2);
                er += __shfl_xor_sync(0xffffffffu, er, 2);
                if ((lane & 3) == 0) {
                    Els[row*8 + wn*4 + j] = el;
                    Ers[row*8 + wn*4 + j] = er;
                }
            }
        }
    }
    __syncthreads();

    #pragma unroll
    for (int i = 0; i < 8; i++) {
        int idx = tid + i*256;
        int row = idx >> 4, cc = idx & 15;
        int gm = n0 + row;
        if (gm < NN)
            *(uint4*)&g_hp[((size_t)r*NN + gm)*128 + cc*8] = *(const uint4*)&Ts[row*ASTRA + cc*8];
    }
    #pragma unroll
    for (int i = 0; i < 4; i++) {
        int idx = tid + i*256;
        int row = idx >> 3;
        if (n0 + row < NN) {
            g_el[((size_t)r*NN + n0)*8 + idx] = Els[idx];
            g_er[((size_t)r*NN + n0)*8 + idx] = Ers[idx];
        }
    }
}

// ---------------- classifier GEMM ----------------
__global__ void __launch_bounds__(256, 2)
k_cls(const float* __restrict__ bc1, const float* __restrict__ wc2,
      const float* __restrict__ bc2, float* __restrict__ out1)
{
    extern __shared__ char smem[];
    __half* Ah = (__half*)smem;
    float* Ps = (float*)(smem + 128*ASTRA*2);
    float* Pt = Ps + 256;

    const int tid  = threadIdx.x;
    const int lane = tid & 31;
    const int w    = tid >> 5;
    const int wm   = w & 3;
    const int wn   = w >> 2;
    const int n0   = blockIdx.x * 128;

    Ps[tid] = (tid < 128) ? bc1[tid] : wc2[tid - 128];

    #pragma unroll
    for (int i = 0; i < 4; i++) {
        int idx = tid + i*256;
        int m = idx >> 3, k = (idx & 7) << 4;
        int gm = n0 + m;
        uint4 z0 = make_uint4(0,0,0,0), z1 = z0;
        if (gm < NN) {
            z0 = *(const uint4*)&g_xh[(size_t)gm*128 + k];
            z1 = *(const uint4*)&g_xh[(size_t)gm*128 + k + 8];
        }
        *(uint4*)&Ah[m*ASTRA + k]     = z0;
        *(uint4*)&Ah[m*ASTRA + k + 8] = z1;
    }
    __syncthreads();

    const uint32_t sAh = smem_u32(Ah);
    const uint32_t aOff = ((wm*32 + (lane & 15))*ASTRA + (lane >> 4)*8) * 2;
    const uint32_t* wf = g_wf + (size_t)6*8*8*128;

    float acc[2][8][4];
    #pragma unroll
    for (int mt = 0; mt < 2; mt++)
        #pragma unroll
        for (int nt = 0; nt < 8; nt++)
            #pragma unroll
            for (int q = 0; q < 4; q++) acc[mt][nt][q] = 0.f;

    #pragma unroll 2
    for (int ks = 0; ks < 8; ks++) {
        uint32_t ah[2][4];
        uint4 b4[4];
        #pragma unroll
        for (int p = 0; p < 4; p++)
            b4[p] = __ldg((const uint4*)(wf + (ks*8 + wn*4 + p)*128) + lane);
        #pragma unroll
        for (int mt = 0; mt < 2; mt++)
            LDSM4(ah[mt], sAh + aOff + mt*(16*ASTRA*2) + ks*32);
        #pragma unroll
        for (int p = 0; p < 4; p++) {
            uint32_t b[4] = {b4[p].x, b4[p].y, b4[p].z, b4[p].w};
            MMA_BLOCK_P(acc, ah, b, p);
        }
    }

    const int g  = lane >> 2;
    const int c2 = (lane & 3) * 2;
    #pragma unroll
    for (int mt = 0; mt < 2; mt++) {
        #pragma unroll
        for (int rh = 0; rh < 2; rh++) {
            float s = 0.f;
            #pragma unroll
            for (int nt = 0; nt < 8; nt++) {
                int n = wn*64 + nt*8 + c2;
                s += fmaxf(acc[mt][nt][rh*2]   + Ps[n],   0.f) * Ps[128+n];
                s += fmaxf(acc[mt][nt][rh*2+1] + Ps[n+1], 0.f) * Ps[128+n+1];
            }
            s += __shfl_xor_sync(0xffffffffu, s, 1);
            s += __shfl_xor_sync(0xffffffffu, s, 2);
            if ((lane & 3) == 0)
                Pt[(wm*32 + mt*16 + rh*8 + g)*2 + wn] = s;
        }
    }
    __syncthreads();
    if (tid < 128) {
        int gm = n0 + tid;
        if (gm < NN) out1[gm] = Pt[tid*2] + Pt[tid*2+1] + bc2[0];
    }
}

// ---------------- warp-per-node aggregate: 16 lanes per edge (2 edges/warp) --
__global__ void k_agg(const float* __restrict__ bias,
                      const float* __restrict__ lng, const float* __restrict__ lnb,
                      int mode)
{
    int warp = (blockIdx.x*blockDim.x + threadIdx.x) >> 5;
    if (warp >= NN) return;
    int v = warp;
    int lane = threadIdx.x & 31;
    int half = lane >> 4;       // which edge of the pair
    int sub  = lane & 15;       // position in row
    int h    = sub >> 1;        // head
    int cb   = sub * 8;         // col base (halves)

    float ax[8];
    #pragma unroll
    for (int j = 0; j < 8; j++) ax[j] = 0.f;

    #pragma unroll
    for (int r = 0; r < RR; r++) {
        int base = r*NN + v;
        int st = g_off[base], d = g_deg[base];
        if (d == 0) continue;
        float erv = __ldg(&g_er[(size_t)base*HH + h]);
        const __half* hpr = g_hp + (size_t)r*NN*DD;
        const float*  elr = g_el + (size_t)r*NN*HH;

        float nx[8];
        #pragma unroll
        for (int j = 0; j < 8; j++) nx[j] = 0.f;
        float den = 0.f;

        int i = 0;
        for (; i + 4 <= d; i += 4) {
            int sa = __ldg(&g_csr[st + i + half]);
            int sb = __ldg(&g_csr[st + i + 2 + half]);
            float xa = __ldg(&elr[(size_t)sa*HH + h]) + erv;
            float xb = __ldg(&elr[(size_t)sb*HH + h]) + erv;
            uint4 ua = *(const uint4*)&hpr[(size_t)sa*DD + cb];
            uint4 ub = *(const uint4*)&hpr[(size_t)sb*DD + cb];
            xa = xa > 0.f ? xa : NEG_SLOPE*xa;
            xb = xb > 0.f ? xb : NEG_SLOPE*xb;
            float qa = __expf(xa), qb = __expf(xb);
            den += qa + qb;
            const __half2* ha = (const __half2*)&ua;
            const __half2* hb = (const __half2*)&ub;
            #pragma unroll
            for (int j = 0; j < 4; j++) {
                float2 fa = __half22float2(ha[j]);
                float2 fb = __half22float2(hb[j]);
                nx[2*j]   += qa*fa.x + qb*fb.x;
                nx[2*j+1] += qa*fa.y + qb*fb.y;
            }
        }
        for (; i < d; i += 2) {
            int idx = i + half;
            bool ok = idx < d;
            int s = ok ? __ldg(&g_csr[st + idx]) : 0;
            float x = __ldg(&elr[(size_t)s*HH + h]) + erv;
            x = x > 0.f ? x : NEG_SLOPE*x;
            float q = ok ? __expf(x) : 0.f;
            den += q;
            uint4 u = *(const uint4*)&hpr[(size_t)s*DD + cb];
            const __half2* hu = (const __half2*)&u;
            #pragma unroll
            for (int j = 0; j < 4; j++) {
                float2 f = __half22float2(hu[j]);
                nx[2*j]   += q*f.x;
                nx[2*j+1] += q*f.y;
            }
        }
        den += __shfl_xor_sync(0xffffffffu, den, 16);
        #pragma unroll
        for (int j = 0; j < 8; j++) nx[j] += __shfl_xor_sync(0xffffffffu, nx[j], 16);
        float rd = 1.0f / den;
        #pragma unroll
        for (int j = 0; j < 8; j++) ax[j] += nx[j]*rd;
    }

    #pragma unroll
    for (int j = 0; j < 8; j++) {
        int c = cb + j;
        ax[j] += bias[c] + bias[128+c] + bias[256+c];
    }

    float o[8];
    if (mode == 0) {
        #pragma unroll
        for (int j = 0; j < 8; j++) o[j] = fmaxf(ax[j], 0.f);
        if (half == 0) {
            *(float4*)&g_h1[(size_t)v*DD + cb]     = make_float4(o[0],o[1],o[2],o[3]);
            *(float4*)&g_h1[(size_t)v*DD + cb + 4] = make_float4(o[4],o[5],o[6],o[7]);
        }
    } else {
        const float* h1p = &g_h1[(size_t)v*DD + cb];
        float4 r0 = *(const float4*)h1p;
        float4 r1 = *(const float4*)(h1p + 4);
        ax[0]+=r0.x; ax[1]+=r0.y; ax[2]+=r0.z; ax[3]+=r0.w;
        ax[4]+=r1.x; ax[5]+=r1.y; ax[6]+=r1.z; ax[7]+=r1.w;
        float s = 0.f, ss = 0.f;
        #pragma unroll
        for (int j = 0; j < 8; j++) { s += ax[j]; ss += ax[j]*ax[j]; }
        #pragma unroll
        for (int o2 = 8; o2; o2 >>= 1) {
            s  += __shfl_xor_sync(0xffffffffu, s,  o2);
            ss += __shfl_xor_sync(0xffffffffu, ss, o2);
        }
        float mu  = s * (1.0f/128.0f);
        float var = ss * (1.0f/128.0f) - mu*mu;
        float inv = rsqrtf(var + LN_EPS);
        #pragma unroll
        for (int j = 0; j < 8; j++)
            o[j] = (ax[j] - mu)*inv*lng[cb+j] + lnb[cb+j];
    }
    if (half == 0) {
        __half hh[8];
        #pragma unroll
        for (int j = 0; j < 8; j++) hh[j] = __float2half_rn(o[j]);
        *(uint4*)&g_xh[(size_t)v*DD + cb] = *(const uint4*)hh;
    }
}

// ---------------- launch ----------------
extern "C" void kernel_launch(void* const* d_in, const int* in_sizes, int n_in,
                              void* d_out, int out_size)
{
    const float* feat = (const float*)d_in[0];
    const int*   esrc = (const int*)d_in[1];
    const int*   edst = (const int*)d_in[2];
    const float* W1   = (const float*)d_in[3];
    const float* al1  = (const float*)d_in[4];
    const float* ar1  = (const float*)d_in[5];
    const float* b1   = (const float*)d_in[6];
    const float* W2   = (const float*)d_in[7];
    const float* al2  = (const float*)d_in[8];
    const float* ar2  = (const float*)d_in[9];
    const float* b2   = (const float*)d_in[10];
    const float* lng  = (const float*)d_in[11];
    const float* lnb  = (const float*)d_in[12];
    const float* Wc1  = (const float*)d_in[13];
    const float* bc1  = (const float*)d_in[14];
    const float* Wc2  = (const float*)d_in[15];
    const float* bc2  = (const float*)d_in[16];
    float* out = (float*)d_out;

    cudaFuncSetAttribute(k_proj, cudaFuncAttributeMaxDynamicSharedMemorySize, SM_PROJ);
    cudaFuncSetAttribute(k_cls,  cudaFuncAttributeMaxDynamicSharedMemorySize, SM_CLS);

    int gx = (NN + 127)/128;
    dim3 gp(gx, RR);
    int aggBlocks = (NN*32 + 255)/256;

    k_setup<<<(NN*16 + 255)/256, 256>>>(W1, W2, Wc1, feat);                // 1
    k_count<<<(RE+255)/256, 256>>>(edst);                                  // 2
    k_assign<<<(RN+255)/256, 256>>>();                                     // 3
    k_fill<<<(RE+255)/256, 256>>>(esrc, edst);                             // 4  <-- profiled
    k_proj<<<gp, 256, SM_PROJ>>>(0, al1, ar1);                             // 5
    k_agg<<<aggBlocks, 256>>>(b1, nullptr, nullptr, 0);                    // 6
    k_proj<<<gp, 256, SM_PROJ>>>(3, al2, ar2);                             // 7
    k_agg<<<aggBlocks, 256>>>(b2, lng, lnb, 1);                            // 8
    k_cls<<<gx, 256, SM_CLS>>>(bc1, Wc2, bc2, out);                        // 9
}